// round 11
// baseline (speedup 1.0000x reference)
#include <cuda_runtime.h>
#include <cuda_fp16.h>
#include <cstdint>

#define GS     256
#define NCLS   10
#define NPTS   262144            // 2^18
#define BATCH  16
#define CELLS  (GS * GS)         // 65536
#define TCELLS (BATCH * CELLS)   // 1,048,576
#define PTOT   (BATCH * NPTS)    // 4,194,304
#define CAP    16                // Poisson(4): P(>16) ~ 1e-6
#define IMGS   (BATCH * NCLS)    // 160
#define OUTN   (IMGS * CELLS)    // 10,485,760 floats

// ---------------------------------------------------------------------------
// Scratch — SLOT-MAJOR 32B records (one sector each):
//   uint4 #0 : v0v1, v2v3, v4v5, v6v7   (half2 bit patterns)
//   uint4 #1 : v8v9 (half2), rx (f32 bits), ry (f32 bits), pad
// ---------------------------------------------------------------------------
__device__ uint32_t g_cursor[TCELLS];
__device__ __align__(128) uint4 g_pay[(size_t)CAP * TCELLS * 2];   // 512 MB

#define OUT4  (OUTN / 4)
#define CUR4  (TCELLS / 4)
__global__ __launch_bounds__(256)
void zero_out_kernel(float4* __restrict__ p, int n4) {
    const int i = blockIdx.x * blockDim.x + threadIdx.x;
    if (i < n4) p[i] = make_float4(0.f, 0.f, 0.f, 0.f);
}
__global__ __launch_bounds__(256)
void zero_cursor_kernel() {
    const int i = blockIdx.x * blockDim.x + threadIdx.x;
    if (i < CUR4) ((uint4*)g_cursor)[i] = make_uint4(0u, 0u, 0u, 0u);
}

__device__ __forceinline__ uint32_t h2bits(float a, float b) {
    __half2 h = __floats2half2_rn(a, b);
    return *reinterpret_cast<uint32_t*>(&h);
}
__device__ __forceinline__ float2 bits2f2(uint32_t u) {
    __half2 h = *reinterpret_cast<__half2*>(&u);
    return __half22float2(h);
}
// packed f32x2 helpers (sm_103a: fma.rn.f32x2 — not emitted by ptxas from C++)
__device__ __forceinline__ unsigned long long pack2(float lo, float hi) {
    unsigned long long r;
    asm("mov.b64 %0, {%1, %2};" : "=l"(r) : "f"(lo), "f"(hi));
    return r;
}
__device__ __forceinline__ void unpack2(unsigned long long v, float& lo, float& hi) {
    asm("mov.b64 {%0, %1}, %2;" : "=f"(lo), "=f"(hi) : "l"(v));
}
__device__ __forceinline__ void ffma2(unsigned long long& d,
                                      unsigned long long a, unsigned long long b) {
    asm("fma.rn.f32x2 %0, %1, %2, %0;" : "+l"(d) : "l"(a), "l"(b));
}

// ---------------------------------------------------------------------------
// Pass A: scatter into fixed-capacity slot-major buckets; overflow -> atomics
// ---------------------------------------------------------------------------
__global__ __launch_bounds__(256)
void scatter_kernel(const float* __restrict__ points,
                    const float* __restrict__ values,
                    float* __restrict__ out) {
    const int gid = blockIdx.x * blockDim.x + threadIdx.x;
    const int b = gid >> 18;
    const int n = gid & (NPTS - 1);

    const float* pb = points + (size_t)b * 2 * NPTS;
    const float fx = (pb[n] + 0.5f) * (float)GS;
    const float fy = (pb[NPTS + n] + 0.5f) * (float)GS;
    const float xf = floorf(fx);
    const float yf = floorf(fy);
    const int x = (int)xf;
    const int y = (int)yf;
    const float rx = fx - xf;
    const float ry = fy - yf;
    if (((unsigned)x >= GS) || ((unsigned)y >= GS)) return;

    const float* vb = values + (size_t)b * NCLS * NPTS + n;
    float v[10];
#pragma unroll
    for (int c = 0; c < NCLS; c++) v[c] = vb[(size_t)c * NPTS];

    const int cellg = (b << 16) + (y << 8) + x;
    const uint32_t slot = atomicAdd(&g_cursor[cellg], 1u);

    if (slot < CAP) {
        uint4* dst = &g_pay[((size_t)slot * TCELLS + cellg) * 2];
        const uint4 q0 = make_uint4(h2bits(v[0], v[1]), h2bits(v[2], v[3]),
                                    h2bits(v[4], v[5]), h2bits(v[6], v[7]));
        const uint4 q1 = make_uint4(h2bits(v[8], v[9]),
                                    __float_as_uint(rx), __float_as_uint(ry), 0u);
        __stcs(dst + 0, q0);
        __stcs(dst + 1, q1);
    } else {
        const bool vx1 = (x + 1) < GS;
        const bool vy1 = (y + 1) < GS;
        const float wx0 = 1.f - rx, wy0 = 1.f - ry;
        const float w00 = wx0 * wy0, w10 = rx * wy0, w01 = wx0 * ry, w11 = rx * ry;
        const int i00 = (y << 8) + x;
        float* ob = out + (size_t)b * NCLS * CELLS;
#pragma unroll
        for (int c = 0; c < NCLS; c++) {
            float* o = ob + ((size_t)c << 16);
            atomicAdd(o + i00, w00 * v[c]);
            if (vx1)        atomicAdd(o + i00 + 1,      w10 * v[c]);
            if (vy1)        atomicAdd(o + i00 + GS,     w01 * v[c]);
            if (vx1 && vy1) atomicAdd(o + i00 + GS + 1, w11 * v[c]);
        }
    }
}

// ---------------------------------------------------------------------------
// Pass B: fused reduce + corner-combine, one THREAD per CELL.
// Packed f32x2 accumulation (20 FFMA2/record), unroll-2 with batched loads.
// Epilogue in two 5-class waves (smem 20KB).
// ---------------------------------------------------------------------------
__global__ __launch_bounds__(256)
void reduce_kernel(float* __restrict__ out) {
    const int t = threadIdx.x;
    const int ly = t >> 4;
    const int lx = t & 15;

    const int blk = blockIdx.x;        // 0..4095
    const int b  = blk >> 8;
    const int tt = blk & 255;
    const int ty = tt >> 4;
    const int tx = tt & 15;

    const int cellg = (b << 16) + ((ty * 16 + ly) << 8) + (tx * 16 + lx);
    const uint32_t raw = g_cursor[cellg];
    const uint32_t cnt = raw < CAP ? raw : CAP;
    const uint32_t wmax = __reduce_max_sync(0xFFFFFFFFu, cnt);

    // acc2[k][j] = packed (class 2j, class 2j+1) sums for corner k
    unsigned long long acc2[4][5];
#pragma unroll
    for (int k = 0; k < 4; k++)
#pragma unroll
        for (int j = 0; j < 5; j++) acc2[k][j] = 0ull;

    for (uint32_t i = 0; i < wmax; i += 2) {
        uint4 q0a, q1a, q0b, q1b;
        const bool pa = (i < cnt);
        const bool pb2 = (i + 1 < cnt);
        if (pa) {                      // batched loads first (MLP)
            const uint4* ra = &g_pay[((size_t)i * TCELLS + cellg) * 2];
            q0a = __ldcs(ra + 0);
            q1a = __ldcs(ra + 1);
        }
        if (pb2) {
            const uint4* rb = &g_pay[((size_t)(i + 1) * TCELLS + cellg) * 2];
            q0b = __ldcs(rb + 0);
            q1b = __ldcs(rb + 1);
        }
        if (pa) {
            const float2 f01 = bits2f2(q0a.x), f23 = bits2f2(q0a.y);
            const float2 f45 = bits2f2(q0a.z), f67 = bits2f2(q0a.w);
            const float2 f89 = bits2f2(q1a.x);
            const float rx = __uint_as_float(q1a.y);
            const float ry = __uint_as_float(q1a.z);
            const float wx0 = 1.f - rx, wy0 = 1.f - ry;
            unsigned long long wp[4] = {
                pack2(wx0 * wy0, wx0 * wy0), pack2(rx * wy0, rx * wy0),
                pack2(wx0 * ry,  wx0 * ry),  pack2(rx * ry,  rx * ry)};
            unsigned long long vp[5] = {
                pack2(f01.x, f01.y), pack2(f23.x, f23.y), pack2(f45.x, f45.y),
                pack2(f67.x, f67.y), pack2(f89.x, f89.y)};
#pragma unroll
            for (int k = 0; k < 4; k++)
#pragma unroll
                for (int j = 0; j < 5; j++) ffma2(acc2[k][j], vp[j], wp[k]);
        }
        if (pb2) {
            const float2 f01 = bits2f2(q0b.x), f23 = bits2f2(q0b.y);
            const float2 f45 = bits2f2(q0b.z), f67 = bits2f2(q0b.w);
            const float2 f89 = bits2f2(q1b.x);
            const float rx = __uint_as_float(q1b.y);
            const float ry = __uint_as_float(q1b.z);
            const float wx0 = 1.f - rx, wy0 = 1.f - ry;
            unsigned long long wp[4] = {
                pack2(wx0 * wy0, wx0 * wy0), pack2(rx * wy0, rx * wy0),
                pack2(wx0 * ry,  wx0 * ry),  pack2(rx * ry,  rx * ry)};
            unsigned long long vp[5] = {
                pack2(f01.x, f01.y), pack2(f23.x, f23.y), pack2(f45.x, f45.y),
                pack2(f67.x, f67.y), pack2(f89.x, f89.y)};
#pragma unroll
            for (int k = 0; k < 4; k++)
#pragma unroll
                for (int j = 0; j < 5; j++) ffma2(acc2[k][j], vp[j], wp[k]);
        }
    }

    // Epilogue in two 5-class waves: smem 4 x 5 x 256 floats = 20KB
    __shared__ float st[4][5][256];
#pragma unroll
    for (int wave = 0; wave < 2; wave++) {
#pragma unroll
        for (int k = 0; k < 4; k++) {
            float lo, hi;
            // classes of this wave: pairs j = wave*2+... wave0 -> j 0,1 + lo of 2; wave1 -> hi of 2 + j 3,4
            if (wave == 0) {
                unpack2(acc2[k][0], lo, hi); st[k][0][t] = lo; st[k][1][t] = hi;
                unpack2(acc2[k][1], lo, hi); st[k][2][t] = lo; st[k][3][t] = hi;
                unpack2(acc2[k][2], lo, hi); st[k][4][t] = lo;
            } else {
                unpack2(acc2[k][2], lo, hi); st[k][0][t] = hi;
                unpack2(acc2[k][3], lo, hi); st[k][1][t] = lo; st[k][2][t] = hi;
                unpack2(acc2[k][4], lo, hi); st[k][3][t] = lo; st[k][4][t] = hi;
            }
        }
        __syncthreads();

        // assemble 17x17 patch for 5 classes: 1445 outputs over 256 threads
        for (int w = t; w < 17 * 17 * 5; w += 256) {
            const int cl = w / 289;                 // 0..4 within wave
            const int r  = w - 289 * cl;
            const int oy = r / 17;
            const int ox = r - 17 * oy;

            float v = 0.f;
            if (oy < 16 && ox < 16)   v += st[0][cl][oy * 16 + ox];
            if (oy < 16 && ox >= 1)   v += st[1][cl][oy * 16 + ox - 1];
            if (oy >= 1 && ox < 16)   v += st[2][cl][(oy - 1) * 16 + ox];
            if (oy >= 1 && ox >= 1)   v += st[3][cl][(oy - 1) * 16 + ox - 1];

            const int Y = ty * 16 + oy;
            const int X = tx * 16 + ox;
            if (Y > 255 || X > 255) continue;

            const int c2 = wave * 5 + cl;
            float* dst = out + (((size_t)(b * NCLS + c2)) << 16) + (Y << 8) + X;
            const bool excl = (oy != 16) && (ox != 16) &&
                              (oy != 0 || ty == 0) && (ox != 0 || tx == 0);
            if (excl) *dst = v + *dst;
            else      atomicAdd(dst, v);
        }
        __syncthreads();   // protect st before next wave overwrites
    }
}

// ---------------------------------------------------------------------------
// Harness entry. Launch order puts reduce at idx 3 (ncu capture slot).
// ---------------------------------------------------------------------------
extern "C" void kernel_launch(void* const* d_in, const int* in_sizes, int n_in,
                              void* d_out, int out_size) {
    const float* points = (const float*)d_in[0];
    const float* values = (const float*)d_in[1];
    float* out = (float*)d_out;

    zero_out_kernel<<<(OUT4 + 255) / 256, 256>>>((float4*)out, OUT4);   // idx 0
    zero_cursor_kernel<<<(CUR4 + 255) / 256, 256>>>();                  // idx 1
    scatter_kernel<<<PTOT / 256, 256>>>(points, values, out);           // idx 2
    reduce_kernel<<<TCELLS / 256, 256>>>(out);                          // idx 3 (profiled)
}